// round 13
// baseline (speedup 1.0000x reference)
#include <cuda_runtime.h>
#include <cuda_bf16.h>
#include <math.h>
#include <stdint.h>

// Problem constants
#define BATCH 2
#define NTOK  2048
#define DMODEL 1024
#define NHEAD 16
#define DHEAD 64
#define HALFW 64          // window is |i-j| <= 64  (129 keys interior)

// Scratch (allocation-free rule: __device__ globals)
__device__ float g_qkv[(size_t)BATCH * NTOK * 3 * DMODEL];           // 50.3 MB
// bf16 hi/lo planes (Dekker split), row-major, same shapes as fp32 sources
__device__ __nv_bfloat16 g_xh[(size_t)BATCH * NTOK * DMODEL];
__device__ __nv_bfloat16 g_xl[(size_t)BATCH * NTOK * DMODEL];
__device__ __nv_bfloat16 g_wqh[(size_t)DMODEL * 3 * DMODEL];
__device__ __nv_bfloat16 g_wql[(size_t)DMODEL * 3 * DMODEL];
__device__ __nv_bfloat16 g_woh[(size_t)DMODEL * DMODEL];
__device__ __nv_bfloat16 g_wol[(size_t)DMODEL * DMODEL];
__device__ __nv_bfloat16 g_ath[(size_t)BATCH * NTOK * DMODEL];
__device__ __nv_bfloat16 g_atl[(size_t)BATCH * NTOK * DMODEL];

// ============================================================================
// helpers (sm_80-era ISA: valid on plain sm_103 target — NO tcgen05)
// ============================================================================
__device__ __forceinline__ uint32_t smem_to_u32(const void* smem_ptr) {
    uint32_t addr;
    asm("{ .reg .u64 tmp; cvta.to.shared.u64 tmp, %1; cvt.u32.u64 %0, tmp; }"
        : "=r"(addr) : "l"(smem_ptr));
    return addr;
}
__device__ __forceinline__ void ldsm_x4(uint32_t* r, uint32_t addr) {
    asm volatile("ldmatrix.sync.aligned.m8n8.x4.shared.b16 {%0,%1,%2,%3}, [%4];"
                 : "=r"(r[0]), "=r"(r[1]), "=r"(r[2]), "=r"(r[3]) : "r"(addr));
}
__device__ __forceinline__ void ldsm_x4_t(uint32_t* r, uint32_t addr) {
    asm volatile("ldmatrix.sync.aligned.m8n8.x4.trans.shared.b16 {%0,%1,%2,%3}, [%4];"
                 : "=r"(r[0]), "=r"(r[1]), "=r"(r[2]), "=r"(r[3]) : "r"(addr));
}
__device__ __forceinline__ void mma2(float* c, const uint32_t* a, uint32_t b0, uint32_t b1) {
    asm volatile(
        "mma.sync.aligned.m16n8k16.row.col.f32.bf16.bf16.f32 "
        "{%0,%1,%2,%3}, {%4,%5,%6,%7}, {%8,%9}, {%0,%1,%2,%3};"
        : "+f"(c[0]), "+f"(c[1]), "+f"(c[2]), "+f"(c[3])
        : "r"(a[0]), "r"(a[1]), "r"(a[2]), "r"(a[3]), "r"(b0), "r"(b1));
}
// pack: lo_v -> low 16 bits, hi_v -> high 16 bits
__device__ __forceinline__ uint32_t cvt2_bf16(float lo_v, float hi_v) {
    uint32_t r;
    asm("cvt.rn.bf16x2.f32 %0, %1, %2;" : "=r"(r) : "f"(hi_v), "f"(lo_v));
    return r;
}
__device__ __forceinline__ void cp16(uint32_t dst, const void* src) {
    asm volatile("cp.async.cg.shared.global [%0], [%1], 16;" :: "r"(dst), "l"(src));
}
#define CP_COMMIT() asm volatile("cp.async.commit_group;" ::: "memory")
#define CP_WAIT(n)  asm volatile("cp.async.wait_group %0;" :: "n"(n) : "memory")

// Dekker split of a float4 into bf16 hi/lo planes; 8B store to each plane.
__device__ __forceinline__ void split_store8(char* dstH, char* dstL, float4 v, uint32_t off) {
    uint32_t h01 = cvt2_bf16(v.x, v.y);
    uint32_t h23 = cvt2_bf16(v.z, v.w);
    float rx = v.x - __uint_as_float(h01 << 16);
    float ry = v.y - __uint_as_float(h01 & 0xFFFF0000u);
    float rz = v.z - __uint_as_float(h23 << 16);
    float rw = v.w - __uint_as_float(h23 & 0xFFFF0000u);
    uint32_t l01 = cvt2_bf16(rx, ry);
    uint32_t l23 = cvt2_bf16(rz, rw);
    *(uint2*)(dstH + off) = make_uint2(h01, h23);
    *(uint2*)(dstL + off) = make_uint2(l01, l23);
}

// ============================================================================
// Split kernel: fp32 array -> bf16 hi/lo planes (grid-stride over float4s)
// ============================================================================
__global__ __launch_bounds__(256)
void split_planes_kernel(const float* __restrict__ in,
                         __nv_bfloat16* __restrict__ hi,
                         __nv_bfloat16* __restrict__ lo, int n4)
{
    int idx = blockIdx.x * 256 + threadIdx.x;
    int stride = gridDim.x * 256;
    for (int i = idx; i < n4; i += stride) {
        float4 v = ((const float4*)in)[i];
        uint32_t h01 = cvt2_bf16(v.x, v.y);
        uint32_t h23 = cvt2_bf16(v.z, v.w);
        float rx = v.x - __uint_as_float(h01 << 16);
        float ry = v.y - __uint_as_float(h01 & 0xFFFF0000u);
        float rz = v.z - __uint_as_float(h23 << 16);
        float rw = v.w - __uint_as_float(h23 & 0xFFFF0000u);
        ((uint2*)hi)[i] = make_uint2(h01, h23);
        ((uint2*)lo)[i] = make_uint2(cvt2_bf16(rx, ry), cvt2_bf16(rz, rw));
    }
}

// ============================================================================
// HMMA GEMM on pre-split bf16 planes:  C = Ah*Bh + Ah*Bl + Al*Bh + bias
// A planes [M,K] row-major bf16, B planes [K,N] row-major bf16.
// CTA tile 128x128, BK=32, 256 threads (8 warps 4m x 2n, warp tile 32x64).
// 4-stage cp.async pipeline; mainloop = LDSM + HMMA only.
// Per stage: Ah/Al [128][40 bf16] (80B rows), Bh/Bl [32][136 bf16] (272B rows).
// ============================================================================
#define SM_AH 0
#define SM_AL 10240
#define SM_BH 20480
#define SM_BL 29184
#define GB    37888                  // bytes per stage
#define PIPE  4
#define GEMM_SMEM_TOTAL (PIPE * GB)

__device__ __forceinline__ void gemm_issue(uint32_t sb_stage,
                                           const char* AhB, const char* AlB,
                                           const char* BhB, const char* BlB,
                                           int kc, int tid, int N, int K)
{
    const int arow = tid >> 2, ac = (tid & 3) * 16;
#pragma unroll
    for (int j = 0; j < 2; ++j) {
        int r = arow + j * 64;
        size_t go = ((size_t)r * K + kc) * 2 + ac;
        uint32_t so = (uint32_t)r * 80 + ac;
        cp16(sb_stage + SM_AH + so, AhB + go);
        cp16(sb_stage + SM_AL + so, AlB + go);
    }
    const int brow = tid >> 4, bc = (tid & 15) * 16;
#pragma unroll
    for (int j = 0; j < 2; ++j) {
        int r = brow + j * 16;
        size_t go = (size_t)(kc + r) * N * 2 + bc;
        uint32_t so = (uint32_t)r * 272 + bc;
        cp16(sb_stage + SM_BH + so, BhB + go);
        cp16(sb_stage + SM_BL + so, BlB + go);
    }
}

__global__ __launch_bounds__(256, 1)
void tc_gemm_bias(const __nv_bfloat16* __restrict__ Ah, const __nv_bfloat16* __restrict__ Al,
                  const __nv_bfloat16* __restrict__ Bh, const __nv_bfloat16* __restrict__ Bl,
                  const float* __restrict__ bias, float* __restrict__ C,
                  int M, int N, int K)
{
    extern __shared__ char smem[];
    const uint32_t smem_base = smem_to_u32(smem);
    const int tid = threadIdx.x;
    const int lane = tid & 31;
    const int wid = tid >> 5;
    const int warp_m = wid & 3;
    const int warp_n = wid >> 2;
    const int bx = blockIdx.x, by = blockIdx.y;

    const char* AhB = (const char*)(Ah + (size_t)by * 128 * K);
    const char* AlB = (const char*)(Al + (size_t)by * 128 * K);
    const char* BhB = (const char*)(Bh + (size_t)bx * 128);
    const char* BlB = (const char*)(Bl + (size_t)bx * 128);

    float acc[2][8][4];
#pragma unroll
    for (int mt = 0; mt < 2; ++mt)
#pragma unroll
        for (int nt = 0; nt < 8; ++nt)
#pragma unroll
            for (int e = 0; e < 4; ++e) acc[mt][nt][e] = 0.0f;

    const uint32_t aAddrBase = smem_base + SM_AH
        + (uint32_t)(warp_m * 32 + (lane & 15)) * 80 + (uint32_t)(lane >> 4) * 16;
    const uint32_t bAddrBase = smem_base + SM_BH
        + (uint32_t)(lane & 15) * 272
        + (uint32_t)warp_n * 128 + (uint32_t)(lane >> 4) * 16;

    const int nchunks = K >> 5;

    // prologue: issue chunks 0..PIPE-2
#pragma unroll
    for (int s = 0; s < PIPE - 1; ++s) {
        gemm_issue(smem_base + (uint32_t)s * GB, AhB, AlB, BhB, BlB, s << 5, tid, N, K);
        CP_COMMIT();
    }

    for (int c = 0; c < nchunks; ++c) {
        const int cn = c + PIPE - 1;
        if (cn < nchunks) {
            gemm_issue(smem_base + (uint32_t)(cn % PIPE) * GB, AhB, AlB, BhB, BlB,
                       cn << 5, tid, N, K);
            CP_COMMIT();
        }
        const int rem = nchunks - 1 - c;
        if (rem >= 3)      { CP_WAIT(3); }
        else if (rem == 2) { CP_WAIT(2); }
        else if (rem == 1) { CP_WAIT(1); }
        else               { CP_WAIT(0); }
        __syncthreads();

        const uint32_t bufr = (uint32_t)(c % PIPE) * GB;
#pragma unroll
        for (int ks = 0; ks < 2; ++ks) {
            uint32_t ah[2][4], al[2][4];
#pragma unroll
            for (int mt = 0; mt < 2; ++mt) {
                uint32_t addr = aAddrBase + bufr + (uint32_t)(mt * 16) * 80 + (uint32_t)ks * 32;
                ldsm_x4(ah[mt], addr);
                ldsm_x4(al[mt], addr + (SM_AL - SM_AH));
            }
            uint32_t bh[4][4], bl[4][4];
#pragma unroll
            for (int ng = 0; ng < 4; ++ng) {
                uint32_t addr = bAddrBase + bufr + (uint32_t)(ks * 16) * 272 + (uint32_t)ng * 32;
                ldsm_x4_t(bh[ng], addr);
                ldsm_x4_t(bl[ng], addr + (SM_BL - SM_BH));
            }
#pragma unroll
            for (int mt = 0; mt < 2; ++mt) {
#pragma unroll
                for (int ng = 0; ng < 4; ++ng) {
                    mma2(acc[mt][2 * ng],     ah[mt], bh[ng][0], bh[ng][1]);
                    mma2(acc[mt][2 * ng],     ah[mt], bl[ng][0], bl[ng][1]);
                    mma2(acc[mt][2 * ng],     al[mt], bh[ng][0], bh[ng][1]);
                    mma2(acc[mt][2 * ng + 1], ah[mt], bh[ng][2], bh[ng][3]);
                    mma2(acc[mt][2 * ng + 1], ah[mt], bl[ng][2], bl[ng][3]);
                    mma2(acc[mt][2 * ng + 1], al[mt], bh[ng][2], bh[ng][3]);
                }
            }
        }
        __syncthreads();   // stage (c%PIPE) free for reuse by issue at c+1
    }

    // ---- epilogue ----
    const int row0 = by * 128 + warp_m * 32 + (lane >> 2);
    const int col0 = bx * 128 + warp_n * 64 + (lane & 3) * 2;
#pragma unroll
    for (int mt = 0; mt < 2; ++mt) {
#pragma unroll
        for (int nt = 0; nt < 8; ++nt) {
            int r = row0 + mt * 16;
            int ccol = col0 + nt * 8;
            float b0 = bias[ccol], b1 = bias[ccol + 1];
            float2 v0 = make_float2(acc[mt][nt][0] + b0, acc[mt][nt][1] + b1);
            float2 v1 = make_float2(acc[mt][nt][2] + b0, acc[mt][nt][3] + b1);
            *(float2*)(C + (size_t)r * N + ccol) = v0;
            *(float2*)(C + (size_t)(r + 8) * N + ccol) = v1;
        }
    }
}

// ============================================================================
// MMA local attention (as R12), epilogue now writes bf16 hi/lo planes so
// GEMM2 consumes pre-split A directly.
// ============================================================================
#define AT_STR 144
#define AQ_H 0
#define AQ_L (AQ_H + 64 * AT_STR)
#define AK_H (AQ_L + 64 * AT_STR)
#define AK_L (AK_H + 192 * AT_STR)
#define AV_H (AK_L + 192 * AT_STR)
#define AV_L (AV_H + 192 * AT_STR)
#define ATTN_SMEM (AV_L + 192 * AT_STR)    // 129024 B

__global__ __launch_bounds__(128, 1)
void attn_mma_kernel()
{
    extern __shared__ char smem[];
    const uint32_t sb = smem_to_u32(smem);
    const int tid = threadIdx.x;
    const int lane = tid & 31, w = tid >> 5;
    const int qt = blockIdx.x, h = blockIdx.y, b = blockIdx.z;
    const int i0 = qt * 64;
    const int jstart = max(0, i0 - HALFW);
    const int jend   = min(NTOK, i0 + 64 + HALFW);
    const int nrows  = jend - jstart;          // 128 or 192

    const float* qkv = g_qkv;

#pragma unroll
    for (int jj = 0; jj < 8; ++jj) {
        int idx = tid + jj * 128;
        int r = idx >> 4, dg = idx & 15;
        float4 v = *(const float4*)(qkv + (size_t)(b * NTOK + i0 + r) * (3 * DMODEL)
                                    + h * DHEAD + dg * 4);
        split_store8(smem + AQ_H, smem + AQ_L, v, (uint32_t)r * AT_STR + dg * 8);
    }
#pragma unroll
    for (int jj = 0; jj < 24; ++jj) {
        int idx = tid + jj * 128;
        int r = idx >> 4, dg = idx & 15;
        if (r < nrows) {
            size_t base = (size_t)(b * NTOK + jstart + r) * (3 * DMODEL) + h * DHEAD + dg * 4;
            float4 kv = *(const float4*)(qkv + base + DMODEL);
            float4 vv = *(const float4*)(qkv + base + 2 * DMODEL);
            uint32_t off = (uint32_t)r * AT_STR + dg * 8;
            split_store8(smem + AK_H, smem + AK_L, kv, off);
            split_store8(smem + AV_H, smem + AV_L, vv, off);
        }
    }
    __syncthreads();

    uint32_t qh[4][4], ql[4][4];
    const uint32_t qaddr = sb + AQ_H + (uint32_t)(w * 16 + (lane & 15)) * AT_STR
                         + (uint32_t)(lane >> 4) * 16;
#pragma unroll
    for (int ks = 0; ks < 4; ++ks) {
        ldsm_x4(qh[ks], qaddr + ks * 32);
        ldsm_x4(ql[ks], qaddr + ks * 32 + (AQ_L - AQ_H));
    }

    float sacc[24][4];
#pragma unroll
    for (int nt = 0; nt < 24; ++nt)
#pragma unroll
        for (int e = 0; e < 4; ++e) sacc[nt][e] = 0.0f;

    const uint32_t kaddr0 = sb + AK_H + (uint32_t)(lane & 15) * AT_STR
                          + (uint32_t)(lane >> 4) * 16;
#pragma unroll
    for (int jt = 0; jt < 12; ++jt) {
        if (jt * 16 < nrows) {
#pragma unroll
            for (int ks = 0; ks < 4; ++ks) {
                uint32_t kh[4], kl[4];
                uint32_t ad = kaddr0 + (uint32_t)(jt * 16) * AT_STR + (uint32_t)ks * 32;
                ldsm_x4(kh, ad);
                ldsm_x4(kl, ad + (AK_L - AK_H));
                mma2(sacc[2 * jt],     qh[ks], kh[0], kh[2]);
                mma2(sacc[2 * jt],     qh[ks], kl[0], kl[2]);
                mma2(sacc[2 * jt],     ql[ks], kh[0], kh[2]);
                mma2(sacc[2 * jt + 1], qh[ks], kh[1], kh[3]);
                mma2(sacc[2 * jt + 1], qh[ks], kl[1], kl[3]);
                mma2(sacc[2 * jt + 1], ql[ks], kh[1], kh[3]);
            }
        }
    }

    const int irow0 = i0 + w * 16 + (lane >> 2);
    const int irow1 = irow0 + 8;
    const int lo0 = irow0 - HALFW, hi0 = irow0 + HALFW;
    const int lo1 = irow1 - HALFW, hi1 = irow1 + HALFW;

    float mx0 = -1e30f, mx1 = -1e30f;
#pragma unroll
    for (int nt = 0; nt < 24; ++nt) {
        int j0 = jstart + nt * 8 + (lane & 3) * 2;
        int j1 = j0 + 1;
        sacc[nt][0] = (j0 < jend && j0 >= lo0 && j0 <= hi0) ? sacc[nt][0] * 0.125f : -1e30f;
        sacc[nt][1] = (j1 < jend && j1 >= lo0 && j1 <= hi0) ? sacc[nt][1] * 0.125f : -1e30f;
        sacc[nt][2] = (j0 < jend && j0 >= lo1 && j0 <= hi1) ? sacc[nt][2] * 0.125f : -1e30f;
        sacc[nt][3] = (j1 < jend && j1 >= lo1 && j1 <= hi1) ? sacc[nt][3] * 0.125f : -1e30f;
        mx0 = fmaxf(mx0, fmaxf(sacc[nt][0], sacc[nt][1]));
        mx1 = fmaxf(mx1, fmaxf(sacc[nt][2], sacc[nt][3]));
    }
    mx0 = fmaxf(mx0, __shfl_xor_sync(0xffffffffu, mx0, 1));
    mx0 = fmaxf(mx0, __shfl_xor_sync(0xffffffffu, mx0, 2));
    mx1 = fmaxf(mx1, __shfl_xor_sync(0xffffffffu, mx1, 1));
    mx1 = fmaxf(mx1, __shfl_xor_sync(0xffffffffu, mx1, 2));

    float sum0 = 0.0f, sum1 = 0.0f;
#pragma unroll
    for (int nt = 0; nt < 24; ++nt) {
        float e0 = __expf(sacc[nt][0] - mx0);
        float e1 = __expf(sacc[nt][1] - mx0);
        float e2 = __expf(sacc[nt][2] - mx1);
        float e3 = __expf(sacc[nt][3] - mx1);
        sacc[nt][0] = e0; sacc[nt][1] = e1; sacc[nt][2] = e2; sacc[nt][3] = e3;
        sum0 += e0 + e1;
        sum1 += e2 + e3;
    }
    sum0 += __shfl_xor_sync(0xffffffffu, sum0, 1);
    sum0 += __shfl_xor_sync(0xffffffffu, sum0, 2);
    sum1 += __shfl_xor_sync(0xffffffffu, sum1, 1);
    sum1 += __shfl_xor_sync(0xffffffffu, sum1, 2);
    const float inv0 = 1.0f / sum0;
    const float inv1 = 1.0f / sum1;

    float out[8][4];
#pragma unroll
    for (int dt = 0; dt < 8; ++dt)
#pragma unroll
        for (int e = 0; e < 4; ++e) out[dt][e] = 0.0f;

    const uint32_t vaddr0 = sb + AV_H + (uint32_t)(lane & 15) * AT_STR
                          + (uint32_t)(lane >> 4) * 16;
#pragma unroll
    for (int kt = 0; kt < 12; ++kt) {
        if (kt * 16 < nrows) {
            const float* t0 = sacc[2 * kt];
            const float* t1 = sacc[2 * kt + 1];
            uint32_t pah[4], pal[4];
            pah[0] = cvt2_bf16(t0[0], t0[1]);
            pah[1] = cvt2_bf16(t0[2], t0[3]);
            pah[2] = cvt2_bf16(t1[0], t1[1]);
            pah[3] = cvt2_bf16(t1[2], t1[3]);
            float r00 = t0[0] - __uint_as_float(pah[0] << 16);
            float r01 = t0[1] - __uint_as_float(pah[0] & 0xFFFF0000u);
            float r02 = t0[2] - __uint_as_float(pah[1] << 16);
            float r03 = t0[3] - __uint_as_float(pah[1] & 0xFFFF0000u);
            float r10 = t1[0] - __uint_as_float(pah[2] << 16);
            float r11 = t1[1] - __uint_as_float(pah[2] & 0xFFFF0000u);
            float r12 = t1[2] - __uint_as_float(pah[3] << 16);
            float r13 = t1[3] - __uint_as_float(pah[3] & 0xFFFF0000u);
            pal[0] = cvt2_bf16(r00, r01);
            pal[1] = cvt2_bf16(r02, r03);
            pal[2] = cvt2_bf16(r10, r11);
            pal[3] = cvt2_bf16(r12, r13);

#pragma unroll
            for (int dp = 0; dp < 4; ++dp) {
                uint32_t vh[4], vl[4];
                uint32_t ad = vaddr0 + (uint32_t)(kt * 16) * AT_STR + (uint32_t)dp * 32;
                ldsm_x4_t(vh, ad);
                ldsm_x4_t(vl, ad + (AV_L - AV_H));
                mma2(out[2 * dp],     pah, vh[0], vh[1]);
                mma2(out[2 * dp],     pah, vl[0], vl[1]);
                mma2(out[2 * dp],     pal, vh[0], vh[1]);
                mma2(out[2 * dp + 1], pah, vh[2], vh[3]);
                mma2(out[2 * dp + 1], pah, vl[2], vl[3]);
                mma2(out[2 * dp + 1], pal, vh[2], vh[3]);
            }
        }
    }

    // ---- epilogue: normalize + Dekker split -> bf16 hi/lo planes ----
#pragma unroll
    for (int dt = 0; dt < 8; ++dt) {
        int d = dt * 8 + (lane & 3) * 2;
        size_t o0 = (size_t)(b * NTOK + irow0) * DMODEL + h * DHEAD + d;
        size_t o1 = (size_t)(b * NTOK + irow1) * DMODEL + h * DHEAD + d;
        float a0 = out[dt][0] * inv0, a1 = out[dt][1] * inv0;
        float a2 = out[dt][2] * inv1, a3 = out[dt][3] * inv1;
        uint32_t h0 = cvt2_bf16(a0, a1);
        uint32_t h1 = cvt2_bf16(a2, a3);
        float r0 = a0 - __uint_as_float(h0 << 16);
        float r1 = a1 - __uint_as_float(h0 & 0xFFFF0000u);
        float r2 = a2 - __uint_as_float(h1 << 16);
        float r3 = a3 - __uint_as_float(h1 & 0xFFFF0000u);
        *(uint32_t*)(g_ath + o0) = h0;
        *(uint32_t*)(g_atl + o0) = cvt2_bf16(r0, r1);
        *(uint32_t*)(g_ath + o1) = h1;
        *(uint32_t*)(g_atl + o1) = cvt2_bf16(r2, r3);
    }
}

// ---------------------------------------------------------------------------
extern "C" void kernel_launch(void* const* d_in, const int* in_sizes, int n_in,
                              void* d_out, int out_size)
{
    const float* x     = (const float*)d_in[0];
    const float* Wqkv  = (const float*)d_in[1];
    const float* bqkv  = (const float*)d_in[2];
    const float* Wout  = (const float*)d_in[3];
    const float* bout  = (const float*)d_in[4];
    float* out = (float*)d_out;

    float* qkv_ptr;
    cudaGetSymbolAddress((void**)&qkv_ptr, g_qkv);
    __nv_bfloat16 *xh, *xl, *wqh, *wql, *woh, *wol, *ath, *atl;
    cudaGetSymbolAddress((void**)&xh,  g_xh);
    cudaGetSymbolAddress((void**)&xl,  g_xl);
    cudaGetSymbolAddress((void**)&wqh, g_wqh);
    cudaGetSymbolAddress((void**)&wql, g_wql);
    cudaGetSymbolAddress((void**)&woh, g_woh);
    cudaGetSymbolAddress((void**)&wol, g_wol);
    cudaGetSymbolAddress((void**)&ath, g_ath);
    cudaGetSymbolAddress((void**)&atl, g_atl);

    cudaFuncSetAttribute(tc_gemm_bias, cudaFuncAttributeMaxDynamicSharedMemorySize,
                         GEMM_SMEM_TOTAL);
    cudaFuncSetAttribute(attn_mma_kernel, cudaFuncAttributeMaxDynamicSharedMemorySize,
                         ATTN_SMEM);

    const int M = BATCH * NTOK;        // 4096

    // Pre-split fp32 -> bf16 hi/lo planes
    split_planes_kernel<<<1024, 256>>>(x,    xh,  xl,  M * DMODEL / 4);
    split_planes_kernel<<<1024, 256>>>(Wqkv, wqh, wql, DMODEL * 3 * DMODEL / 4);
    split_planes_kernel<<<1024, 256>>>(Wout, woh, wol, DMODEL * DMODEL / 4);

    // GEMM1: qkv = x @ Wqkv + bqkv   [4096 x 3072]
    dim3 g1(3 * DMODEL / 128, M / 128);
    tc_gemm_bias<<<g1, 256, GEMM_SMEM_TOTAL>>>(xh, xl, wqh, wql, bqkv, qkv_ptr,
                                               M, 3 * DMODEL, DMODEL);

    // Local attention -> att planes
    dim3 ga(NTOK / 64, NHEAD, BATCH);
    attn_mma_kernel<<<ga, 128, ATTN_SMEM>>>();

    // GEMM2: out = att @ Wout + bout  [4096 x 1024]
    dim3 g2(DMODEL / 128, M / 128);
    tc_gemm_bias<<<g2, 256, GEMM_SMEM_TOTAL>>>(ath, atl, woh, wol, bout, out,
                                               M, DMODEL, DMODEL);
}

// round 16
// speedup vs baseline: 1.0615x; 1.0615x over previous
#include <cuda_runtime.h>
#include <cuda_bf16.h>
#include <math.h>
#include <stdint.h>

// Problem constants
#define BATCH 2
#define NTOK  2048
#define DMODEL 1024
#define NHEAD 16
#define DHEAD 64
#define HALFW 64          // window is |i-j| <= 64  (129 keys interior)

// Scratch (allocation-free rule: __device__ globals)
__device__ float g_qkv[(size_t)BATCH * NTOK * 3 * DMODEL];           // 50.3 MB
// bf16 hi/lo planes (Dekker split), row-major, same shapes as fp32 sources
__device__ __nv_bfloat16 g_xh[(size_t)BATCH * NTOK * DMODEL];
__device__ __nv_bfloat16 g_xl[(size_t)BATCH * NTOK * DMODEL];
__device__ __nv_bfloat16 g_wqh[(size_t)DMODEL * 3 * DMODEL];
__device__ __nv_bfloat16 g_wql[(size_t)DMODEL * 3 * DMODEL];
__device__ __nv_bfloat16 g_woh[(size_t)DMODEL * DMODEL];
__device__ __nv_bfloat16 g_wol[(size_t)DMODEL * DMODEL];
__device__ __nv_bfloat16 g_ath[(size_t)BATCH * NTOK * DMODEL];
__device__ __nv_bfloat16 g_atl[(size_t)BATCH * NTOK * DMODEL];

// ============================================================================
// helpers (sm_80-era ISA: valid on plain sm_103 target — NO tcgen05)
// ============================================================================
__device__ __forceinline__ uint32_t smem_to_u32(const void* smem_ptr) {
    uint32_t addr;
    asm("{ .reg .u64 tmp; cvta.to.shared.u64 tmp, %1; cvt.u32.u64 %0, tmp; }"
        : "=r"(addr) : "l"(smem_ptr));
    return addr;
}
__device__ __forceinline__ void ldsm_x4(uint32_t* r, uint32_t addr) {
    asm volatile("ldmatrix.sync.aligned.m8n8.x4.shared.b16 {%0,%1,%2,%3}, [%4];"
                 : "=r"(r[0]), "=r"(r[1]), "=r"(r[2]), "=r"(r[3]) : "r"(addr));
}
__device__ __forceinline__ void ldsm_x4_t(uint32_t* r, uint32_t addr) {
    asm volatile("ldmatrix.sync.aligned.m8n8.x4.trans.shared.b16 {%0,%1,%2,%3}, [%4];"
                 : "=r"(r[0]), "=r"(r[1]), "=r"(r[2]), "=r"(r[3]) : "r"(addr));
}
__device__ __forceinline__ void mma2(float* c, const uint32_t* a, uint32_t b0, uint32_t b1) {
    asm volatile(
        "mma.sync.aligned.m16n8k16.row.col.f32.bf16.bf16.f32 "
        "{%0,%1,%2,%3}, {%4,%5,%6,%7}, {%8,%9}, {%0,%1,%2,%3};"
        : "+f"(c[0]), "+f"(c[1]), "+f"(c[2]), "+f"(c[3])
        : "r"(a[0]), "r"(a[1]), "r"(a[2]), "r"(a[3]), "r"(b0), "r"(b1));
}
// pack: lo_v -> low 16 bits, hi_v -> high 16 bits
__device__ __forceinline__ uint32_t cvt2_bf16(float lo_v, float hi_v) {
    uint32_t r;
    asm("cvt.rn.bf16x2.f32 %0, %1, %2;" : "=r"(r) : "f"(hi_v), "f"(lo_v));
    return r;
}
__device__ __forceinline__ void cp16(uint32_t dst, const void* src) {
    asm volatile("cp.async.cg.shared.global [%0], [%1], 16;" :: "r"(dst), "l"(src));
}
#define CP_COMMIT() asm volatile("cp.async.commit_group;" ::: "memory")
#define CP_WAIT(n)  asm volatile("cp.async.wait_group %0;" :: "n"(n) : "memory")

// Dekker split of a float4 into bf16 hi/lo planes; 8B store to each plane.
__device__ __forceinline__ void split_store8(char* dstH, char* dstL, float4 v, uint32_t off) {
    uint32_t h01 = cvt2_bf16(v.x, v.y);
    uint32_t h23 = cvt2_bf16(v.z, v.w);
    float rx = v.x - __uint_as_float(h01 << 16);
    float ry = v.y - __uint_as_float(h01 & 0xFFFF0000u);
    float rz = v.z - __uint_as_float(h23 << 16);
    float rw = v.w - __uint_as_float(h23 & 0xFFFF0000u);
    uint32_t l01 = cvt2_bf16(rx, ry);
    uint32_t l23 = cvt2_bf16(rz, rw);
    *(uint2*)(dstH + off) = make_uint2(h01, h23);
    *(uint2*)(dstL + off) = make_uint2(l01, l23);
}

// ============================================================================
// Split kernel: fp32 array -> bf16 hi/lo planes (grid-stride over float4s)
// ============================================================================
__global__ __launch_bounds__(256)
void split_planes_kernel(const float* __restrict__ in,
                         __nv_bfloat16* __restrict__ hi,
                         __nv_bfloat16* __restrict__ lo, int n4)
{
    int idx = blockIdx.x * 256 + threadIdx.x;
    int stride = gridDim.x * 256;
    for (int i = idx; i < n4; i += stride) {
        float4 v = ((const float4*)in)[i];
        uint32_t h01 = cvt2_bf16(v.x, v.y);
        uint32_t h23 = cvt2_bf16(v.z, v.w);
        float rx = v.x - __uint_as_float(h01 << 16);
        float ry = v.y - __uint_as_float(h01 & 0xFFFF0000u);
        float rz = v.z - __uint_as_float(h23 << 16);
        float rw = v.w - __uint_as_float(h23 & 0xFFFF0000u);
        ((uint2*)hi)[i] = make_uint2(h01, h23);
        ((uint2*)lo)[i] = make_uint2(cvt2_bf16(rx, ry), cvt2_bf16(rz, rw));
    }
}

// ============================================================================
// HMMA GEMM on pre-split bf16 planes:  C = Ah*Bh + Ah*Bl + Al*Bh + bias
// CTA tile 128x128, BK=32, **512 threads** (16 warps 4m x 4n, warp tile 32x32)
// -> 4 warps/SMSP for latency hiding. 3-stage cp.async pipeline, ONE
// __syncthreads per chunk (wait -> sync -> issue -> compute ordering).
// Per stage: Ah/Al [128][40 bf16] (80B rows), Bh/Bl [32][136 bf16] (272B rows).
// ============================================================================
#define SM_AH 0
#define SM_AL 10240
#define SM_BH 20480
#define SM_BL 29184
#define GB    37888                  // bytes per stage
#define PIPE  3
#define GEMM_SMEM_TOTAL (PIPE * GB)  // 113664

__device__ __forceinline__ void gemm_issue(uint32_t sb_stage,
                                           const char* AhB, const char* AlB,
                                           const char* BhB, const char* BlB,
                                           int kc, int tid, int N, int K)
{
    // A planes: 128 rows x 64B; 512 transfers/plane -> 1 cp16/thread/plane
    {
        const int r = tid >> 2, ac = (tid & 3) * 16;
        size_t go = ((size_t)r * K + kc) * 2 + ac;
        uint32_t so = (uint32_t)r * 80 + ac;
        cp16(sb_stage + SM_AH + so, AhB + go);
        cp16(sb_stage + SM_AL + so, AlB + go);
    }
    // B planes: 32 rows x 256B; 512 transfers/plane -> 1 cp16/thread/plane
    {
        const int r = tid >> 4, bc = (tid & 15) * 16;
        size_t go = (size_t)(kc + r) * N * 2 + bc;
        uint32_t so = (uint32_t)r * 272 + bc;
        cp16(sb_stage + SM_BH + so, BhB + go);
        cp16(sb_stage + SM_BL + so, BlB + go);
    }
}

__global__ __launch_bounds__(512, 1)
void tc_gemm_bias(const __nv_bfloat16* __restrict__ Ah, const __nv_bfloat16* __restrict__ Al,
                  const __nv_bfloat16* __restrict__ Bh, const __nv_bfloat16* __restrict__ Bl,
                  const float* __restrict__ bias, float* __restrict__ C,
                  int M, int N, int K)
{
    extern __shared__ char smem[];
    const uint32_t smem_base = smem_to_u32(smem);
    const int tid = threadIdx.x;
    const int lane = tid & 31;
    const int wid = tid >> 5;
    const int warp_m = wid & 3;       // 32-row slice
    const int warp_n = wid >> 2;      // 32-col slice
    const int bx = blockIdx.x, by = blockIdx.y;

    const char* AhB = (const char*)(Ah + (size_t)by * 128 * K);
    const char* AlB = (const char*)(Al + (size_t)by * 128 * K);
    const char* BhB = (const char*)(Bh + (size_t)bx * 128);
    const char* BlB = (const char*)(Bl + (size_t)bx * 128);

    float acc[2][4][4];
#pragma unroll
    for (int mt = 0; mt < 2; ++mt)
#pragma unroll
        for (int nt = 0; nt < 4; ++nt)
#pragma unroll
            for (int e = 0; e < 4; ++e) acc[mt][nt][e] = 0.0f;

    const uint32_t aAddrBase = smem_base + SM_AH
        + (uint32_t)(warp_m * 32 + (lane & 15)) * 80 + (uint32_t)(lane >> 4) * 16;
    const uint32_t bAddrBase = smem_base + SM_BH
        + (uint32_t)(lane & 15) * 272
        + (uint32_t)warp_n * 64 + (uint32_t)(lane >> 4) * 16;

    const int nchunks = K >> 5;

    // prologue: issue chunks 0..PIPE-2
#pragma unroll
    for (int s = 0; s < PIPE - 1; ++s) {
        gemm_issue(smem_base + (uint32_t)s * GB, AhB, AlB, BhB, BlB, s << 5, tid, N, K);
        CP_COMMIT();
    }

    for (int c = 0; c < nchunks; ++c) {
        // chunk c complete when <= PIPE-2 groups outstanding
        const int rem = nchunks - 1 - c;
        if (rem >= PIPE - 2) { CP_WAIT(PIPE - 2); }
        else                 { CP_WAIT(0); }
        __syncthreads();   // all warps past compute(c-1); stage (c-1)%PIPE free

        const int cn = c + PIPE - 1;
        if (cn < nchunks) {
            gemm_issue(smem_base + (uint32_t)(cn % PIPE) * GB, AhB, AlB, BhB, BlB,
                       cn << 5, tid, N, K);
            CP_COMMIT();
        }

        const uint32_t bufr = (uint32_t)(c % PIPE) * GB;
#pragma unroll
        for (int ks = 0; ks < 2; ++ks) {
            uint32_t ah[2][4], al[2][4];
#pragma unroll
            for (int mt = 0; mt < 2; ++mt) {
                uint32_t addr = aAddrBase + bufr + (uint32_t)(mt * 16) * 80 + (uint32_t)ks * 32;
                ldsm_x4(ah[mt], addr);
                ldsm_x4(al[mt], addr + (SM_AL - SM_AH));
            }
            uint32_t bh[2][4], bl[2][4];
#pragma unroll
            for (int ng = 0; ng < 2; ++ng) {
                uint32_t addr = bAddrBase + bufr + (uint32_t)(ks * 16) * 272 + (uint32_t)ng * 32;
                ldsm_x4_t(bh[ng], addr);
                ldsm_x4_t(bl[ng], addr + (SM_BL - SM_BH));
            }
#pragma unroll
            for (int mt = 0; mt < 2; ++mt) {
#pragma unroll
                for (int ng = 0; ng < 2; ++ng) {
                    mma2(acc[mt][2 * ng],     ah[mt], bh[ng][0], bh[ng][1]);
                    mma2(acc[mt][2 * ng],     ah[mt], bl[ng][0], bl[ng][1]);
                    mma2(acc[mt][2 * ng],     al[mt], bh[ng][0], bh[ng][1]);
                    mma2(acc[mt][2 * ng + 1], ah[mt], bh[ng][2], bh[ng][3]);
                    mma2(acc[mt][2 * ng + 1], ah[mt], bl[ng][2], bl[ng][3]);
                    mma2(acc[mt][2 * ng + 1], al[mt], bh[ng][2], bh[ng][3]);
                }
            }
        }
    }

    // ---- epilogue ----
    const int row0 = by * 128 + warp_m * 32 + (lane >> 2);
    const int col0 = bx * 128 + warp_n * 32 + (lane & 3) * 2;
#pragma unroll
    for (int mt = 0; mt < 2; ++mt) {
#pragma unroll
        for (int nt = 0; nt < 4; ++nt) {
            int r = row0 + mt * 16;
            int ccol = col0 + nt * 8;
            float b0 = bias[ccol], b1 = bias[ccol + 1];
            float2 v0 = make_float2(acc[mt][nt][0] + b0, acc[mt][nt][1] + b1);
            float2 v1 = make_float2(acc[mt][nt][2] + b0, acc[mt][nt][3] + b1);
            *(float2*)(C + (size_t)r * N + ccol) = v0;
            *(float2*)(C + (size_t)(r + 8) * N + ccol) = v1;
        }
    }
}

// ============================================================================
// MMA local attention (as R12), epilogue writes bf16 hi/lo planes so GEMM2
// consumes pre-split A directly.
// ============================================================================
#define AT_STR 144
#define AQ_H 0
#define AQ_L (AQ_H + 64 * AT_STR)
#define AK_H (AQ_L + 64 * AT_STR)
#define AK_L (AK_H + 192 * AT_STR)
#define AV_H (AK_L + 192 * AT_STR)
#define AV_L (AV_H + 192 * AT_STR)
#define ATTN_SMEM (AV_L + 192 * AT_STR)    // 129024 B

__global__ __launch_bounds__(128, 1)
void attn_mma_kernel()
{
    extern __shared__ char smem[];
    const uint32_t sb = smem_to_u32(smem);
    const int tid = threadIdx.x;
    const int lane = tid & 31, w = tid >> 5;
    const int qt = blockIdx.x, h = blockIdx.y, b = blockIdx.z;
    const int i0 = qt * 64;
    const int jstart = max(0, i0 - HALFW);
    const int jend   = min(NTOK, i0 + 64 + HALFW);
    const int nrows  = jend - jstart;          // 128 or 192

    const float* qkv = g_qkv;

#pragma unroll
    for (int jj = 0; jj < 8; ++jj) {
        int idx = tid + jj * 128;
        int r = idx >> 4, dg = idx & 15;
        float4 v = *(const float4*)(qkv + (size_t)(b * NTOK + i0 + r) * (3 * DMODEL)
                                    + h * DHEAD + dg * 4);
        split_store8(smem + AQ_H, smem + AQ_L, v, (uint32_t)r * AT_STR + dg * 8);
    }
#pragma unroll
    for (int jj = 0; jj < 24; ++jj) {
        int idx = tid + jj * 128;
        int r = idx >> 4, dg = idx & 15;
        if (r < nrows) {
            size_t base = (size_t)(b * NTOK + jstart + r) * (3 * DMODEL) + h * DHEAD + dg * 4;
            float4 kv = *(const float4*)(qkv + base + DMODEL);
            float4 vv = *(const float4*)(qkv + base + 2 * DMODEL);
            uint32_t off = (uint32_t)r * AT_STR + dg * 8;
            split_store8(smem + AK_H, smem + AK_L, kv, off);
            split_store8(smem + AV_H, smem + AV_L, vv, off);
        }
    }
    __syncthreads();

    uint32_t qh[4][4], ql[4][4];
    const uint32_t qaddr = sb + AQ_H + (uint32_t)(w * 16 + (lane & 15)) * AT_STR
                         + (uint32_t)(lane >> 4) * 16;
#pragma unroll
    for (int ks = 0; ks < 4; ++ks) {
        ldsm_x4(qh[ks], qaddr + ks * 32);
        ldsm_x4(ql[ks], qaddr + ks * 32 + (AQ_L - AQ_H));
    }

    float sacc[24][4];
#pragma unroll
    for (int nt = 0; nt < 24; ++nt)
#pragma unroll
        for (int e = 0; e < 4; ++e) sacc[nt][e] = 0.0f;

    const uint32_t kaddr0 = sb + AK_H + (uint32_t)(lane & 15) * AT_STR
                          + (uint32_t)(lane >> 4) * 16;
#pragma unroll
    for (int jt = 0; jt < 12; ++jt) {
        if (jt * 16 < nrows) {
#pragma unroll
            for (int ks = 0; ks < 4; ++ks) {
                uint32_t kh[4], kl[4];
                uint32_t ad = kaddr0 + (uint32_t)(jt * 16) * AT_STR + (uint32_t)ks * 32;
                ldsm_x4(kh, ad);
                ldsm_x4(kl, ad + (AK_L - AK_H));
                mma2(sacc[2 * jt],     qh[ks], kh[0], kh[2]);
                mma2(sacc[2 * jt],     qh[ks], kl[0], kl[2]);
                mma2(sacc[2 * jt],     ql[ks], kh[0], kh[2]);
                mma2(sacc[2 * jt + 1], qh[ks], kh[1], kh[3]);
                mma2(sacc[2 * jt + 1], qh[ks], kl[1], kl[3]);
                mma2(sacc[2 * jt + 1], ql[ks], kh[1], kh[3]);
            }
        }
    }

    const int irow0 = i0 + w * 16 + (lane >> 2);
    const int irow1 = irow0 + 8;
    const int lo0 = irow0 - HALFW, hi0 = irow0 + HALFW;
    const int lo1 = irow1 - HALFW, hi1 = irow1 + HALFW;

    float mx0 = -1e30f, mx1 = -1e30f;
#pragma unroll
    for (int nt = 0; nt < 24; ++nt) {
        int j0 = jstart + nt * 8 + (lane & 3) * 2;
        int j1 = j0 + 1;
        sacc[nt][0] = (j0 < jend && j0 >= lo0 && j0 <= hi0) ? sacc[nt][0] * 0.125f : -1e30f;
        sacc[nt][1] = (j1 < jend && j1 >= lo0 && j1 <= hi0) ? sacc[nt][1] * 0.125f : -1e30f;
        sacc[nt][2] = (j0 < jend && j0 >= lo1 && j0 <= hi1) ? sacc[nt][2] * 0.125f : -1e30f;
        sacc[nt][3] = (j1 < jend && j1 >= lo1 && j1 <= hi1) ? sacc[nt][3] * 0.125f : -1e30f;
        mx0 = fmaxf(mx0, fmaxf(sacc[nt][0], sacc[nt][1]));
        mx1 = fmaxf(mx1, fmaxf(sacc[nt][2], sacc[nt][3]));
    }
    mx0 = fmaxf(mx0, __shfl_xor_sync(0xffffffffu, mx0, 1));
    mx0 = fmaxf(mx0, __shfl_xor_sync(0xffffffffu, mx0, 2));
    mx1 = fmaxf(mx1, __shfl_xor_sync(0xffffffffu, mx1, 1));
    mx1 = fmaxf(mx1, __shfl_xor_sync(0xffffffffu, mx1, 2));

    float sum0 = 0.0f, sum1 = 0.0f;
#pragma unroll
    for (int nt = 0; nt < 24; ++nt) {
        float e0 = __expf(sacc[nt][0] - mx0);
        float e1 = __expf(sacc[nt][1] - mx0);
        float e2 = __expf(sacc[nt][2] - mx1);
        float e3 = __expf(sacc[nt][3] - mx1);
        sacc[nt][0] = e0; sacc[nt][1] = e1; sacc[nt][2] = e2; sacc[nt][3] = e3;
        sum0 += e0 + e1;
        sum1 += e2 + e3;
    }
    sum0 += __shfl_xor_sync(0xffffffffu, sum0, 1);
    sum0 += __shfl_xor_sync(0xffffffffu, sum0, 2);
    sum1 += __shfl_xor_sync(0xffffffffu, sum1, 1);
    sum1 += __shfl_xor_sync(0xffffffffu, sum1, 2);
    const float inv0 = 1.0f / sum0;
    const float inv1 = 1.0f / sum1;

    float out[8][4];
#pragma unroll
    for (int dt = 0; dt < 8; ++dt)
#pragma unroll
        for (int e = 0; e < 4; ++e) out[dt][e] = 0.0f;

    const uint32_t vaddr0 = sb + AV_H + (uint32_t)(lane & 15) * AT_STR
                          + (uint32_t)(lane >> 4) * 16;
#pragma unroll
    for (int kt = 0; kt < 12; ++kt) {
        if (kt * 16 < nrows) {
            const float* t0 = sacc[2 * kt];
            const float* t1 = sacc[2 * kt + 1];
            uint32_t pah[4], pal[4];
            pah[0] = cvt2_bf16(t0[0], t0[1]);
            pah[1] = cvt2_bf16(t0[2], t0[3]);
            pah[2] = cvt2_bf16(t1[0], t1[1]);
            pah[3] = cvt2_bf16(t1[2], t1[3]);
            float r00 = t0[0] - __uint_as_float(pah[0] << 16);
            float r01 = t0[1] - __uint_as_float(pah[0] & 0xFFFF0000u);
            float r02 = t0[2] - __uint_as_float(pah[1] << 16);
            float r03 = t0[3] - __uint_as_float(pah[1] & 0xFFFF0000u);
            float r10 = t1[0] - __uint_as_float(pah[2] << 16);
            float r11 = t1[1] - __uint_as_float(pah[2] & 0xFFFF0000u);
            float r12 = t1[2] - __uint_as_float(pah[3] << 16);
            float r13 = t1[3] - __uint_as_float(pah[3] & 0xFFFF0000u);
            pal[0] = cvt2_bf16(r00, r01);
            pal[1] = cvt2_bf16(r02, r03);
            pal[2] = cvt2_bf16(r10, r11);
            pal[3] = cvt2_bf16(r12, r13);

#pragma unroll
            for (int dp = 0; dp < 4; ++dp) {
                uint32_t vh[4], vl[4];
                uint32_t ad = vaddr0 + (uint32_t)(kt * 16) * AT_STR + (uint32_t)dp * 32;
                ldsm_x4_t(vh, ad);
                ldsm_x4_t(vl, ad + (AV_L - AV_H));
                mma2(out[2 * dp],     pah, vh[0], vh[1]);
                mma2(out[2 * dp],     pah, vl[0], vl[1]);
                mma2(out[2 * dp],     pal, vh[0], vh[1]);
                mma2(out[2 * dp + 1], pah, vh[2], vh[3]);
                mma2(out[2 * dp + 1], pah, vl[2], vl[3]);
                mma2(out[2 * dp + 1], pal, vh[2], vh[3]);
            }
        }
    }

    // ---- epilogue: normalize + Dekker split -> bf16 hi/lo planes ----
#pragma unroll
    for (int dt = 0; dt < 8; ++dt) {
        int d = dt * 8 + (lane & 3) * 2;
        size_t o0 = (size_t)(b * NTOK + irow0) * DMODEL + h * DHEAD + d;
        size_t o1 = (size_t)(b * NTOK + irow1) * DMODEL + h * DHEAD + d;
        float a0 = out[dt][0] * inv0, a1 = out[dt][1] * inv0;
        float a2 = out[dt][2] * inv1, a3 = out[dt][3] * inv1;
        uint32_t h0 = cvt2_bf16(a0, a1);
        uint32_t h1 = cvt2_bf16(a2, a3);
        float r0 = a0 - __uint_as_float(h0 << 16);
        float r1 = a1 - __uint_as_float(h0 & 0xFFFF0000u);
        float r2 = a2 - __uint_as_float(h1 << 16);
        float r3 = a3 - __uint_as_float(h1 & 0xFFFF0000u);
        *(uint32_t*)(g_ath + o0) = h0;
        *(uint32_t*)(g_atl + o0) = cvt2_bf16(r0, r1);
        *(uint32_t*)(g_ath + o1) = h1;
        *(uint32_t*)(g_atl + o1) = cvt2_bf16(r2, r3);
    }
}

// ---------------------------------------------------------------------------
extern "C" void kernel_launch(void* const* d_in, const int* in_sizes, int n_in,
                              void* d_out, int out_size)
{
    const float* x     = (const float*)d_in[0];
    const float* Wqkv  = (const float*)d_in[1];
    const float* bqkv  = (const float*)d_in[2];
    const float* Wout  = (const float*)d_in[3];
    const float* bout  = (const float*)d_in[4];
    float* out = (float*)d_out;

    float* qkv_ptr;
    cudaGetSymbolAddress((void**)&qkv_ptr, g_qkv);
    __nv_bfloat16 *xh, *xl, *wqh, *wql, *woh, *wol, *ath, *atl;
    cudaGetSymbolAddress((void**)&xh,  g_xh);
    cudaGetSymbolAddress((void**)&xl,  g_xl);
    cudaGetSymbolAddress((void**)&wqh, g_wqh);
    cudaGetSymbolAddress((void**)&wql, g_wql);
    cudaGetSymbolAddress((void**)&woh, g_woh);
    cudaGetSymbolAddress((void**)&wol, g_wol);
    cudaGetSymbolAddress((void**)&ath, g_ath);
    cudaGetSymbolAddress((void**)&atl, g_atl);

    cudaFuncSetAttribute(tc_gemm_bias, cudaFuncAttributeMaxDynamicSharedMemorySize,
                         GEMM_SMEM_TOTAL);
    cudaFuncSetAttribute(attn_mma_kernel, cudaFuncAttributeMaxDynamicSharedMemorySize,
                         ATTN_SMEM);

    const int M = BATCH * NTOK;        // 4096

    // Pre-split fp32 -> bf16 hi/lo planes
    split_planes_kernel<<<1024, 256>>>(x,    xh,  xl,  M * DMODEL / 4);
    split_planes_kernel<<<1024, 256>>>(Wqkv, wqh, wql, DMODEL * 3 * DMODEL / 4);
    split_planes_kernel<<<1024, 256>>>(Wout, woh, wol, DMODEL * DMODEL / 4);

    // GEMM1: qkv = x @ Wqkv + bqkv   [4096 x 3072]
    dim3 g1(3 * DMODEL / 128, M / 128);
    tc_gemm_bias<<<g1, 512, GEMM_SMEM_TOTAL>>>(xh, xl, wqh, wql, bqkv, qkv_ptr,
                                               M, 3 * DMODEL, DMODEL);

    // Local attention -> att planes
    dim3 ga(NTOK / 64, NHEAD, BATCH);
    attn_mma_kernel<<<ga, 128, ATTN_SMEM>>>();

    // GEMM2: out = att @ Wout + bout  [4096 x 1024]
    dim3 g2(DMODEL / 128, M / 128);
    tc_gemm_bias<<<g2, 512, GEMM_SMEM_TOTAL>>>(ath, atl, woh, wol, bout, out,
                                               M, DMODEL, DMODEL);
}

// round 17
// speedup vs baseline: 1.4199x; 1.3376x over previous
#include <cuda_runtime.h>
#include <cuda_fp16.h>
#include <math.h>
#include <stdint.h>

// Problem constants
#define BATCH 2
#define NTOK  2048
#define DMODEL 1024
#define NHEAD 16
#define DHEAD 64
#define HALFW 64          // window is |i-j| <= 64  (129 keys interior)

// Scratch (allocation-free rule: __device__ globals)
__device__ float g_qkv[(size_t)BATCH * NTOK * 3 * DMODEL];           // 50.3 MB
// fp16 planes: A-side matrices get Dekker hi/lo; B-side (weights) single.
__device__ __half g_xh[(size_t)BATCH * NTOK * DMODEL];
__device__ __half g_xl[(size_t)BATCH * NTOK * DMODEL];
__device__ __half g_wq16[(size_t)DMODEL * 3 * DMODEL];
__device__ __half g_wo16[(size_t)DMODEL * DMODEL];
__device__ __half g_ath[(size_t)BATCH * NTOK * DMODEL];
__device__ __half g_atl[(size_t)BATCH * NTOK * DMODEL];

// ============================================================================
// helpers (sm_80-era ISA: valid on plain sm_103 target — NO tcgen05)
// ============================================================================
__device__ __forceinline__ uint32_t smem_to_u32(const void* smem_ptr) {
    uint32_t addr;
    asm("{ .reg .u64 tmp; cvta.to.shared.u64 tmp, %1; cvt.u32.u64 %0, tmp; }"
        : "=r"(addr) : "l"(smem_ptr));
    return addr;
}
__device__ __forceinline__ void ldsm_x4(uint32_t* r, uint32_t addr) {
    asm volatile("ldmatrix.sync.aligned.m8n8.x4.shared.b16 {%0,%1,%2,%3}, [%4];"
                 : "=r"(r[0]), "=r"(r[1]), "=r"(r[2]), "=r"(r[3]) : "r"(addr));
}
__device__ __forceinline__ void ldsm_x4_t(uint32_t* r, uint32_t addr) {
    asm volatile("ldmatrix.sync.aligned.m8n8.x4.trans.shared.b16 {%0,%1,%2,%3}, [%4];"
                 : "=r"(r[0]), "=r"(r[1]), "=r"(r[2]), "=r"(r[3]) : "r"(addr));
}
// fp16 MMA, fp32 accumulate
__device__ __forceinline__ void mma2h(float* c, const uint32_t* a, uint32_t b0, uint32_t b1) {
    asm volatile(
        "mma.sync.aligned.m16n8k16.row.col.f32.f16.f16.f32 "
        "{%0,%1,%2,%3}, {%4,%5,%6,%7}, {%8,%9}, {%0,%1,%2,%3};"
        : "+f"(c[0]), "+f"(c[1]), "+f"(c[2]), "+f"(c[3])
        : "r"(a[0]), "r"(a[1]), "r"(a[2]), "r"(a[3]), "r"(b0), "r"(b1));
}
__device__ __forceinline__ uint32_t h2_u32(__half2 h) { return *(uint32_t*)&h; }
__device__ __forceinline__ void cp16(uint32_t dst, const void* src) {
    asm volatile("cp.async.cg.shared.global [%0], [%1], 16;" :: "r"(dst), "l"(src));
}
#define CP_COMMIT() asm volatile("cp.async.commit_group;" ::: "memory")
#define CP_WAIT(n)  asm volatile("cp.async.wait_group %0;" :: "n"(n) : "memory")

// fp16 single-plane store of a float4 (8 bytes)
__device__ __forceinline__ void store8h(char* dst, float4 v, uint32_t off) {
    __half2 h01 = __floats2half2_rn(v.x, v.y);
    __half2 h23 = __floats2half2_rn(v.z, v.w);
    *(uint2*)(dst + off) = make_uint2(h2_u32(h01), h2_u32(h23));
}
// fp16 Dekker split store: hi plane + residual lo plane
__device__ __forceinline__ void split_store8h(char* dstH, char* dstL, float4 v, uint32_t off) {
    __half2 h01 = __floats2half2_rn(v.x, v.y);
    __half2 h23 = __floats2half2_rn(v.z, v.w);
    float2 f01 = __half22float2(h01);
    float2 f23 = __half22float2(h23);
    __half2 l01 = __floats2half2_rn(v.x - f01.x, v.y - f01.y);
    __half2 l23 = __floats2half2_rn(v.z - f23.x, v.w - f23.y);
    *(uint2*)(dstH + off) = make_uint2(h2_u32(h01), h2_u32(h23));
    *(uint2*)(dstL + off) = make_uint2(h2_u32(l01), h2_u32(l23));
}

// ============================================================================
// Split kernels
// ============================================================================
__global__ __launch_bounds__(256)
void split2_f16_kernel(const float* __restrict__ in,
                       __half* __restrict__ hi, __half* __restrict__ lo, int n4)
{
    int idx = blockIdx.x * 256 + threadIdx.x;
    int stride = gridDim.x * 256;
    for (int i = idx; i < n4; i += stride) {
        float4 v = ((const float4*)in)[i];
        __half2 h01 = __floats2half2_rn(v.x, v.y);
        __half2 h23 = __floats2half2_rn(v.z, v.w);
        float2 f01 = __half22float2(h01);
        float2 f23 = __half22float2(h23);
        ((uint2*)hi)[i] = make_uint2(h2_u32(h01), h2_u32(h23));
        ((uint2*)lo)[i] = make_uint2(
            h2_u32(__floats2half2_rn(v.x - f01.x, v.y - f01.y)),
            h2_u32(__floats2half2_rn(v.z - f23.x, v.w - f23.y)));
    }
}
__global__ __launch_bounds__(256)
void cvt_f16_kernel(const float* __restrict__ in, __half* __restrict__ hi, int n4)
{
    int idx = blockIdx.x * 256 + threadIdx.x;
    int stride = gridDim.x * 256;
    for (int i = idx; i < n4; i += stride) {
        float4 v = ((const float4*)in)[i];
        ((uint2*)hi)[i] = make_uint2(h2_u32(__floats2half2_rn(v.x, v.y)),
                                     h2_u32(__floats2half2_rn(v.z, v.w)));
    }
}

// ============================================================================
// HMMA GEMM, fp16 2-pass:  C = Ah*B + Al*B + bias
// A planes [M,K] fp16 hi/lo, B [K,N] single fp16.
// CTA tile 128x128, BK=32, 512 threads (16 warps 4m x 4n, warp tile 32x32).
// 3-stage cp.async pipeline, one __syncthreads per chunk.
// Per stage: Ah/Al [128][40 h] (80B rows), B [32][136 h] (272B rows).
// ============================================================================
#define SM_AH 0
#define SM_AL 10240
#define SM_B  20480
#define GB    29184                  // bytes per stage
#define PIPE  3
#define GEMM_SMEM_TOTAL (PIPE * GB)  // 87552

__device__ __forceinline__ void gemm_issue(uint32_t sb_stage,
                                           const char* AhB, const char* AlB,
                                           const char* BB,
                                           int kc, int tid, int N, int K)
{
    {
        const int r = tid >> 2, ac = (tid & 3) * 16;
        size_t go = ((size_t)r * K + kc) * 2 + ac;
        uint32_t so = (uint32_t)r * 80 + ac;
        cp16(sb_stage + SM_AH + so, AhB + go);
        cp16(sb_stage + SM_AL + so, AlB + go);
    }
    {
        const int r = tid >> 4, bc = (tid & 15) * 16;
        size_t go = (size_t)(kc + r) * N * 2 + bc;
        uint32_t so = (uint32_t)r * 272 + bc;
        cp16(sb_stage + SM_B + so, BB + go);
    }
}

__global__ __launch_bounds__(512, 1)
void tc_gemm_bias(const __half* __restrict__ Ah, const __half* __restrict__ Al,
                  const __half* __restrict__ Bm,
                  const float* __restrict__ bias, float* __restrict__ C,
                  int M, int N, int K)
{
    extern __shared__ char smem[];
    const uint32_t smem_base = smem_to_u32(smem);
    const int tid = threadIdx.x;
    const int lane = tid & 31;
    const int wid = tid >> 5;
    const int warp_m = wid & 3;
    const int warp_n = wid >> 2;
    const int bx = blockIdx.x, by = blockIdx.y;

    const char* AhB = (const char*)(Ah + (size_t)by * 128 * K);
    const char* AlB = (const char*)(Al + (size_t)by * 128 * K);
    const char* BB  = (const char*)(Bm + (size_t)bx * 128);

    float acc[2][4][4];
#pragma unroll
    for (int mt = 0; mt < 2; ++mt)
#pragma unroll
        for (int nt = 0; nt < 4; ++nt)
#pragma unroll
            for (int e = 0; e < 4; ++e) acc[mt][nt][e] = 0.0f;

    const uint32_t aAddrBase = smem_base + SM_AH
        + (uint32_t)(warp_m * 32 + (lane & 15)) * 80 + (uint32_t)(lane >> 4) * 16;
    const uint32_t bAddrBase = smem_base + SM_B
        + (uint32_t)(lane & 15) * 272
        + (uint32_t)warp_n * 64 + (uint32_t)(lane >> 4) * 16;

    const int nchunks = K >> 5;

#pragma unroll
    for (int s = 0; s < PIPE - 1; ++s) {
        gemm_issue(smem_base + (uint32_t)s * GB, AhB, AlB, BB, s << 5, tid, N, K);
        CP_COMMIT();
    }

    for (int c = 0; c < nchunks; ++c) {
        const int rem = nchunks - 1 - c;
        if (rem >= PIPE - 2) { CP_WAIT(PIPE - 2); }
        else                 { CP_WAIT(0); }
        __syncthreads();

        const int cn = c + PIPE - 1;
        if (cn < nchunks) {
            gemm_issue(smem_base + (uint32_t)(cn % PIPE) * GB, AhB, AlB, BB,
                       cn << 5, tid, N, K);
            CP_COMMIT();
        }

        const uint32_t bufr = (uint32_t)(c % PIPE) * GB;
#pragma unroll
        for (int ks = 0; ks < 2; ++ks) {
            uint32_t ah[2][4], al[2][4];
#pragma unroll
            for (int mt = 0; mt < 2; ++mt) {
                uint32_t addr = aAddrBase + bufr + (uint32_t)(mt * 16) * 80 + (uint32_t)ks * 32;
                ldsm_x4(ah[mt], addr);
                ldsm_x4(al[mt], addr + (SM_AL - SM_AH));
            }
            uint32_t bh[2][4];
#pragma unroll
            for (int ng = 0; ng < 2; ++ng) {
                uint32_t addr = bAddrBase + bufr + (uint32_t)(ks * 16) * 272 + (uint32_t)ng * 32;
                ldsm_x4_t(bh[ng], addr);
            }
#pragma unroll
            for (int mt = 0; mt < 2; ++mt) {
#pragma unroll
                for (int ng = 0; ng < 2; ++ng) {
                    mma2h(acc[mt][2 * ng],     ah[mt], bh[ng][0], bh[ng][1]);
                    mma2h(acc[mt][2 * ng],     al[mt], bh[ng][0], bh[ng][1]);
                    mma2h(acc[mt][2 * ng + 1], ah[mt], bh[ng][2], bh[ng][3]);
                    mma2h(acc[mt][2 * ng + 1], al[mt], bh[ng][2], bh[ng][3]);
                }
            }
        }
    }

    // ---- epilogue ----
    const int row0 = by * 128 + warp_m * 32 + (lane >> 2);
    const int col0 = bx * 128 + warp_n * 32 + (lane & 3) * 2;
#pragma unroll
    for (int mt = 0; mt < 2; ++mt) {
#pragma unroll
        for (int nt = 0; nt < 4; ++nt) {
            int r = row0 + mt * 16;
            int ccol = col0 + nt * 8;
            float b0 = bias[ccol], b1 = bias[ccol + 1];
            float2 v0 = make_float2(acc[mt][nt][0] + b0, acc[mt][nt][1] + b1);
            float2 v1 = make_float2(acc[mt][nt][2] + b0, acc[mt][nt][3] + b1);
            *(float2*)(C + (size_t)r * N + ccol) = v0;
            *(float2*)(C + (size_t)(r + 8) * N + ccol) = v1;
        }
    }
}

// ============================================================================
// MMA local attention, fp16 2-pass (Q and P Dekker-split; K, V single fp16).
// Block = (q-tile 64, head, batch), 128 threads. Epilogue writes fp16 hi/lo
// planes so GEMM2 consumes pre-split A directly.
// ============================================================================
#define AT_STR 144
#define AQ_H 0
#define AQ_L (AQ_H + 64 * AT_STR)
#define AK_  (AQ_L + 64 * AT_STR)
#define AV_  (AK_ + 192 * AT_STR)
#define ATTN_SMEM (AV_ + 192 * AT_STR)     // 73728 B

__global__ __launch_bounds__(128, 1)
void attn_mma_kernel()
{
    extern __shared__ char smem[];
    const uint32_t sb = smem_to_u32(smem);
    const int tid = threadIdx.x;
    const int lane = tid & 31, w = tid >> 5;
    const int qt = blockIdx.x, h = blockIdx.y, b = blockIdx.z;
    const int i0 = qt * 64;
    const int jstart = max(0, i0 - HALFW);
    const int jend   = min(NTOK, i0 + 64 + HALFW);
    const int nrows  = jend - jstart;          // 128 or 192

    const float* qkv = g_qkv;

#pragma unroll
    for (int jj = 0; jj < 8; ++jj) {
        int idx = tid + jj * 128;
        int r = idx >> 4, dg = idx & 15;
        float4 v = *(const float4*)(qkv + (size_t)(b * NTOK + i0 + r) * (3 * DMODEL)
                                    + h * DHEAD + dg * 4);
        split_store8h(smem + AQ_H, smem + AQ_L, v, (uint32_t)r * AT_STR + dg * 8);
    }
#pragma unroll
    for (int jj = 0; jj < 24; ++jj) {
        int idx = tid + jj * 128;
        int r = idx >> 4, dg = idx & 15;
        if (r < nrows) {
            size_t base = (size_t)(b * NTOK + jstart + r) * (3 * DMODEL) + h * DHEAD + dg * 4;
            float4 kv = *(const float4*)(qkv + base + DMODEL);
            float4 vv = *(const float4*)(qkv + base + 2 * DMODEL);
            uint32_t off = (uint32_t)r * AT_STR + dg * 8;
            store8h(smem + AK_, kv, off);
            store8h(smem + AV_, vv, off);
        }
    }
    __syncthreads();

    uint32_t qh[4][4], ql[4][4];
    const uint32_t qaddr = sb + AQ_H + (uint32_t)(w * 16 + (lane & 15)) * AT_STR
                         + (uint32_t)(lane >> 4) * 16;
#pragma unroll
    for (int ks = 0; ks < 4; ++ks) {
        ldsm_x4(qh[ks], qaddr + ks * 32);
        ldsm_x4(ql[ks], qaddr + ks * 32 + (AQ_L - AQ_H));
    }

    float sacc[24][4];
#pragma unroll
    for (int nt = 0; nt < 24; ++nt)
#pragma unroll
        for (int e = 0; e < 4; ++e) sacc[nt][e] = 0.0f;

    const uint32_t kaddr0 = sb + AK_ + (uint32_t)(lane & 15) * AT_STR
                          + (uint32_t)(lane >> 4) * 16;
#pragma unroll
    for (int jt = 0; jt < 12; ++jt) {
        if (jt * 16 < nrows) {
#pragma unroll
            for (int ks = 0; ks < 4; ++ks) {
                uint32_t kh[4];
                uint32_t ad = kaddr0 + (uint32_t)(jt * 16) * AT_STR + (uint32_t)ks * 32;
                ldsm_x4(kh, ad);
                mma2h(sacc[2 * jt],     qh[ks], kh[0], kh[2]);
                mma2h(sacc[2 * jt],     ql[ks], kh[0], kh[2]);
                mma2h(sacc[2 * jt + 1], qh[ks], kh[1], kh[3]);
                mma2h(sacc[2 * jt + 1], ql[ks], kh[1], kh[3]);
            }
        }
    }

    const int irow0 = i0 + w * 16 + (lane >> 2);
    const int irow1 = irow0 + 8;
    const int lo0 = irow0 - HALFW, hi0 = irow0 + HALFW;
    const int lo1 = irow1 - HALFW, hi1 = irow1 + HALFW;

    float mx0 = -1e30f, mx1 = -1e30f;
#pragma unroll
    for (int nt = 0; nt < 24; ++nt) {
        int j0 = jstart + nt * 8 + (lane & 3) * 2;
        int j1 = j0 + 1;
        sacc[nt][0] = (j0 < jend && j0 >= lo0 && j0 <= hi0) ? sacc[nt][0] * 0.125f : -1e30f;
        sacc[nt][1] = (j1 < jend && j1 >= lo0 && j1 <= hi0) ? sacc[nt][1] * 0.125f : -1e30f;
        sacc[nt][2] = (j0 < jend && j0 >= lo1 && j0 <= hi1) ? sacc[nt][2] * 0.125f : -1e30f;
        sacc[nt][3] = (j1 < jend && j1 >= lo1 && j1 <= hi1) ? sacc[nt][3] * 0.125f : -1e30f;
        mx0 = fmaxf(mx0, fmaxf(sacc[nt][0], sacc[nt][1]));
        mx1 = fmaxf(mx1, fmaxf(sacc[nt][2], sacc[nt][3]));
    }
    mx0 = fmaxf(mx0, __shfl_xor_sync(0xffffffffu, mx0, 1));
    mx0 = fmaxf(mx0, __shfl_xor_sync(0xffffffffu, mx0, 2));
    mx1 = fmaxf(mx1, __shfl_xor_sync(0xffffffffu, mx1, 1));
    mx1 = fmaxf(mx1, __shfl_xor_sync(0xffffffffu, mx1, 2));

    float sum0 = 0.0f, sum1 = 0.0f;
#pragma unroll
    for (int nt = 0; nt < 24; ++nt) {
        float e0 = __expf(sacc[nt][0] - mx0);
        float e1 = __expf(sacc[nt][1] - mx0);
        float e2 = __expf(sacc[nt][2] - mx1);
        float e3 = __expf(sacc[nt][3] - mx1);
        sacc[nt][0] = e0; sacc[nt][1] = e1; sacc[nt][2] = e2; sacc[nt][3] = e3;
        sum0 += e0 + e1;
        sum1 += e2 + e3;
    }
    sum0 += __shfl_xor_sync(0xffffffffu, sum0, 1);
    sum0 += __shfl_xor_sync(0xffffffffu, sum0, 2);
    sum1 += __shfl_xor_sync(0xffffffffu, sum1, 1);
    sum1 += __shfl_xor_sync(0xffffffffu, sum1, 2);
    const float inv0 = 1.0f / sum0;
    const float inv1 = 1.0f / sum1;

    float out[8][4];
#pragma unroll
    for (int dt = 0; dt < 8; ++dt)
#pragma unroll
        for (int e = 0; e < 4; ++e) out[dt][e] = 0.0f;

    const uint32_t vaddr0 = sb + AV_ + (uint32_t)(lane & 15) * AT_STR
                          + (uint32_t)(lane >> 4) * 16;
#pragma unroll
    for (int kt = 0; kt < 12; ++kt) {
        if (kt * 16 < nrows) {
            const float* t0 = sacc[2 * kt];
            const float* t1 = sacc[2 * kt + 1];
            uint32_t pah[4], pal[4];
            __half2 p0 = __floats2half2_rn(t0[0], t0[1]);
            __half2 p1 = __floats2half2_rn(t0[2], t0[3]);
            __half2 p2 = __floats2half2_rn(t1[0], t1[1]);
            __half2 p3 = __floats2half2_rn(t1[2], t1[3]);
            pah[0] = h2_u32(p0); pah[1] = h2_u32(p1);
            pah[2] = h2_u32(p2); pah[3] = h2_u32(p3);
            float2 f0 = __half22float2(p0), f1 = __half22float2(p1);
            float2 f2 = __half22float2(p2), f3 = __half22float2(p3);
            pal[0] = h2_u32(__floats2half2_rn(t0[0] - f0.x, t0[1] - f0.y));
            pal[1] = h2_u32(__floats2half2_rn(t0[2] - f1.x, t0[3] - f1.y));
            pal[2] = h2_u32(__floats2half2_rn(t1[0] - f2.x, t1[1] - f2.y));
            pal[3] = h2_u32(__floats2half2_rn(t1[2] - f3.x, t1[3] - f3.y));

#pragma unroll
            for (int dp = 0; dp < 4; ++dp) {
                uint32_t vh[4];
                uint32_t ad = vaddr0 + (uint32_t)(kt * 16) * AT_STR + (uint32_t)dp * 32;
                ldsm_x4_t(vh, ad);
                mma2h(out[2 * dp],     pah, vh[0], vh[1]);
                mma2h(out[2 * dp],     pal, vh[0], vh[1]);
                mma2h(out[2 * dp + 1], pah, vh[2], vh[3]);
                mma2h(out[2 * dp + 1], pal, vh[2], vh[3]);
            }
        }
    }

    // ---- epilogue: normalize + fp16 Dekker split -> hi/lo planes ----
#pragma unroll
    for (int dt = 0; dt < 8; ++dt) {
        int d = dt * 8 + (lane & 3) * 2;
        size_t o0 = (size_t)(b * NTOK + irow0) * DMODEL + h * DHEAD + d;
        size_t o1 = (size_t)(b * NTOK + irow1) * DMODEL + h * DHEAD + d;
        float a0 = out[dt][0] * inv0, a1 = out[dt][1] * inv0;
        float a2 = out[dt][2] * inv1, a3 = out[dt][3] * inv1;
        __half2 h0 = __floats2half2_rn(a0, a1);
        __half2 h1 = __floats2half2_rn(a2, a3);
        float2 f0 = __half22float2(h0), f1 = __half22float2(h1);
        *(uint32_t*)(g_ath + o0) = h2_u32(h0);
        *(uint32_t*)(g_atl + o0) = h2_u32(__floats2half2_rn(a0 - f0.x, a1 - f0.y));
        *(uint32_t*)(g_ath + o1) = h2_u32(h1);
        *(uint32_t*)(g_atl + o1) = h2_u32(__floats2half2_rn(a2 - f1.x, a3 - f1.y));
    }
}

// ---------------------------------------------------------------------------
extern "C" void kernel_launch(void* const* d_in, const int* in_sizes, int n_in,
                              void* d_out, int out_size)
{
    const float* x     = (const float*)d_in[0];
    const float* Wqkv  = (const float*)d_in[1];
    const float* bqkv  = (const float*)d_in[2];
    const float* Wout  = (const float*)d_in[3];
    const float* bout  = (const float*)d_in[4];
    float* out = (float*)d_out;

    float* qkv_ptr;
    cudaGetSymbolAddress((void**)&qkv_ptr, g_qkv);
    __half *xh, *xl, *wq16, *wo16, *ath, *atl;
    cudaGetSymbolAddress((void**)&xh,   g_xh);
    cudaGetSymbolAddress((void**)&xl,   g_xl);
    cudaGetSymbolAddress((void**)&wq16, g_wq16);
    cudaGetSymbolAddress((void**)&wo16, g_wo16);
    cudaGetSymbolAddress((void**)&ath,  g_ath);
    cudaGetSymbolAddress((void**)&atl,  g_atl);

    cudaFuncSetAttribute(tc_gemm_bias, cudaFuncAttributeMaxDynamicSharedMemorySize,
                         GEMM_SMEM_TOTAL);
    cudaFuncSetAttribute(attn_mma_kernel, cudaFuncAttributeMaxDynamicSharedMemorySize,
                         ATTN_SMEM);

    const int M = BATCH * NTOK;        // 4096

    // Pre-split / convert fp32 -> fp16 planes
    split2_f16_kernel<<<1024, 256>>>(x, xh, xl, M * DMODEL / 4);
    cvt_f16_kernel<<<1024, 256>>>(Wqkv, wq16, DMODEL * 3 * DMODEL / 4);
    cvt_f16_kernel<<<512, 256>>>(Wout, wo16, DMODEL * DMODEL / 4);

    // GEMM1: qkv = x @ Wqkv + bqkv   [4096 x 3072]
    dim3 g1(3 * DMODEL / 128, M / 128);
    tc_gemm_bias<<<g1, 512, GEMM_SMEM_TOTAL>>>(xh, xl, wq16, bqkv, qkv_ptr,
                                               M, 3 * DMODEL, DMODEL);

    // Local attention -> att fp16 planes
    dim3 ga(NTOK / 64, NHEAD, BATCH);
    attn_mma_kernel<<<ga, 128, ATTN_SMEM>>>();

    // GEMM2: out = att @ Wout + bout  [4096 x 1024]
    dim3 g2(DMODEL / 128, M / 128);
    tc_gemm_bias<<<g2, 512, GEMM_SMEM_TOTAL>>>(ath, atl, wo16, bout, out,
                                               M, DMODEL, DMODEL);
}